// round 9
// baseline (speedup 1.0000x reference)
#include <cuda_runtime.h>
#include <cstdint>

// Locally-connected layer:
//   out[b,o,i,j] = sum_{c,ki,kj} x[b,c,i+ki,j+kj] * w[o,c,i,j,ki*3+kj] + bias[o,i,j]
// Shapes: x[128,32,34,34] f32, w[64,32,32,32,9] f32, bias[64,32,32] f32,
//         out[128,64,32,32] f32.
// One block per (i,j): GEMM M=128(b) x N=64(o) x K=288(c*9+k) with
// position-private weights. f32x2 packed FMAs, cp.async double-buffered K chunks.

#define B_    128
#define CIN   32
#define COUT  64
#define HW    34
#define KC    72      // 8 input channels * 9 taps per chunk
#define NCH   4       // 4 chunks * 72 = 288
#define WPAD  68      // padded row stride for W tile (floats)

#define SMEM_FLOATS (2*KC*128 + 2*KC*WPAD)   // 18432 + 9792 = 28224 floats
#define SMEM_BYTES  (SMEM_FLOATS * 4)        // 112896 B

__device__ __forceinline__ void cp4(uint32_t dst, const float* src) {
    asm volatile("cp.async.ca.shared.global [%0], [%1], 4;\n" :: "r"(dst), "l"(src));
}
__device__ __forceinline__ void cp_commit() {
    asm volatile("cp.async.commit_group;\n");
}
template <int N>
__device__ __forceinline__ void cp_wait() {
    asm volatile("cp.async.wait_group %0;\n" :: "n"(N));
}

__device__ __forceinline__ unsigned long long pack2(float v) {
    unsigned long long r;
    asm("mov.b64 %0, {%1, %1};" : "=l"(r) : "f"(v));
    return r;
}
__device__ __forceinline__ void ffma2(unsigned long long& acc,
                                      unsigned long long a,
                                      unsigned long long b) {
    asm("fma.rn.f32x2 %0, %1, %2, %0;" : "+l"(acc) : "l"(a), "l"(b));
}

__global__ void __launch_bounds__(256, 2)
lc_kernel(const float* __restrict__ x,
          const float* __restrict__ w,
          const float* __restrict__ bias,
          float* __restrict__ out)
{
    extern __shared__ float sm[];
    float* As = sm;                 // [2][KC][128]  x-patches, k-major, b contiguous
    float* Ws = sm + 2 * KC * 128;  // [2][KC][WPAD] weights,   k-major, o contiguous

    const int bx  = blockIdx.x;
    const int i   = bx >> 5;
    const int j   = bx & 31;
    const int pos = i * 32 + j;
    const int tid = threadIdx.x;

    // Compute-tile coordinates: 16 m-threads (8 b each) x 16 n-threads (4 o each).
    // Warp covers 32m x 32n; within a warp, 8 lanes share each A address
    // (broadcast) and 4 lanes share each W address; all LDS.128 conflict-free.
    const int warp = tid >> 5, lane = tid & 31;
    const int wm = warp & 3,  wn = warp >> 2;
    const int lm = lane >> 3, ln = lane & 7;
    const int m0 = (wm * 4 + lm) * 8;   // batch base (0..120)
    const int n0 = (wn * 8 + ln) * 4;   // out-channel base (0..60)

    unsigned long long acc[4][4];
    #pragma unroll
    for (int p = 0; p < 4; ++p)
        #pragma unroll
        for (int q = 0; q < 4; ++q) acc[p][q] = 0ull;

    // ---- chunk loaders (cp.async, 4B granules) ----
    auto loadA = [&](int kc, int buf) {
        float* dst0 = As + buf * KC * 128;
        const int c0 = kc * 8;
        #pragma unroll
        for (int r = 0; r < 36; ++r) {                 // 36*256 = 9216 = 72*128
            int idx = tid + 256 * r;
            int row = idx / 384;                       // row = cc*3 + ki  (0..23)
            int rem = idx - row * 384;
            int b   = rem / 3;
            int kj  = rem - b * 3;
            int cc  = row / 3;
            int ki  = row - cc * 3;
            const float* src =
                x + ((b * CIN + c0 + cc) * HW + (i + ki)) * HW + (j + kj);
            cp4((uint32_t)__cvta_generic_to_shared(dst0 + (row * 3 + kj) * 128 + b),
                src);
        }
    };
    auto loadW = [&](int kc, int buf) {
        float* dst0 = Ws + buf * KC * WPAD;
        const int c0 = kc * 8;
        #pragma unroll
        for (int r = 0; r < 18; ++r) {                 // 18*256 = 4608 = 72*64
            int idx = tid + 256 * r;
            int o   = idx / KC;
            int kk  = idx - o * KC;                    // kk = cc*9 + k9
            int cc  = kk / 9;
            int k9  = kk - cc * 9;
            const float* src =
                w + ((o * CIN + c0 + cc) * 1024 + pos) * 9 + k9;
            cp4((uint32_t)__cvta_generic_to_shared(dst0 + kk * WPAD + o), src);
        }
    };

    // ---- pipelined mainloop ----
    loadA(0, 0); loadW(0, 0); cp_commit();

    for (int t = 0; t < NCH; ++t) {
        if (t + 1 < NCH) {
            loadA(t + 1, (t + 1) & 1);
            loadW(t + 1, (t + 1) & 1);
            cp_commit();
            cp_wait<1>();            // chunk t's group is complete
        } else {
            cp_wait<0>();
        }
        __syncthreads();

        const float* A  = As + (t & 1) * KC * 128 + m0;
        const float* Wt = Ws + (t & 1) * KC * WPAD + n0;

        #pragma unroll 4
        for (int k = 0; k < KC; ++k) {
            ulonglong2 a01 = *(const ulonglong2*)(A + k * 128);      // b pairs 0,1
            ulonglong2 a23 = *(const ulonglong2*)(A + k * 128 + 4);  // b pairs 2,3
            float4 wv = *(const float4*)(Wt + k * WPAD);
            unsigned long long w0 = pack2(wv.x);
            unsigned long long w1 = pack2(wv.y);
            unsigned long long w2 = pack2(wv.z);
            unsigned long long w3 = pack2(wv.w);

            ffma2(acc[0][0], a01.x, w0); ffma2(acc[0][1], a01.x, w1);
            ffma2(acc[0][2], a01.x, w2); ffma2(acc[0][3], a01.x, w3);
            ffma2(acc[1][0], a01.y, w0); ffma2(acc[1][1], a01.y, w1);
            ffma2(acc[1][2], a01.y, w2); ffma2(acc[1][3], a01.y, w3);
            ffma2(acc[2][0], a23.x, w0); ffma2(acc[2][1], a23.x, w1);
            ffma2(acc[2][2], a23.x, w2); ffma2(acc[2][3], a23.x, w3);
            ffma2(acc[3][0], a23.y, w0); ffma2(acc[3][1], a23.y, w1);
            ffma2(acc[3][2], a23.y, w2); ffma2(acc[3][3], a23.y, w3);
        }
        __syncthreads();
    }

    // ---- epilogue: bias + scattered stores (L2 merges across j-adjacent blocks) ----
    float bv[4];
    #pragma unroll
    for (int q = 0; q < 4; ++q) bv[q] = bias[(n0 + q) * 1024 + pos];

    float* outp = out + pos;
    #pragma unroll
    for (int p = 0; p < 4; ++p) {
        const int bb = m0 + 2 * p;
        #pragma unroll
        for (int q = 0; q < 4; ++q) {
            float2 v = *(float2*)&acc[p][q];
            const int o = n0 + q;
            outp[(bb * COUT + o) * 1024]       = v.x + bv[q];
            outp[((bb + 1) * COUT + o) * 1024] = v.y + bv[q];
        }
    }
}

extern "C" void kernel_launch(void* const* d_in, const int* in_sizes, int n_in,
                              void* d_out, int out_size)
{
    (void)in_sizes; (void)n_in; (void)out_size;
    const float* x    = (const float*)d_in[0];
    const float* w    = (const float*)d_in[1];
    const float* bias = (const float*)d_in[2];
    float* out        = (float*)d_out;

    cudaFuncSetAttribute(lc_kernel,
                         cudaFuncAttributeMaxDynamicSharedMemorySize, SMEM_BYTES);
    lc_kernel<<<1024, 256, SMEM_BYTES>>>(x, w, bias, out);
}

// round 11
// speedup vs baseline: 1.0738x; 1.0738x over previous
#include <cuda_runtime.h>
#include <cstdint>

// out[b,o,i,j] = sum_{c,ki,kj} x[b,c,i+ki,j+kj] * w[o,c,i,j,ki*3+kj] + bias[o,i,j]
// x[128,32,34,34] f32, w[64,32,32,32,9], bias[64,32,32], out[128,64,32,32].
//
// Kernel 1 (lc_gemm): one block per (i,j). GEMM M=128(b) x N=64(o) x K=288,
//   128 threads, 8m x 8n register tiles, f32x2 FMAs packed along n (W pairs
//   read natively from o-contiguous smem). A stored as [row][b][float4]
//   (cols j-lead..j-lead+3) so cp.async can use 16B/8B granules.
//   Writes scratch[pos][b][o] fully coalesced.
// Kernel 2 (transpose_k): scratch[pos][bo] -> out[bo][pos] via 32x33 smem tile.

#define CIN   32
#define COUT  64
#define HW    34
#define NPOS  1024
#define NCH   8      // K chunks
#define CPC   4      // input channels per chunk
#define RPC   12     // A rows per chunk (CPC*3)
#define KKPC  36     // k values per chunk (CPC*9)

#define AS_FLOATS (2*RPC*128*4)        // 12288 floats (49152 B), float4 slots
#define WS_FLOATS (2*KKPC*64)          // 4608 floats  (18432 B)
#define SMEM_BYTES ((AS_FLOATS + WS_FLOATS)*4)   // 67584 B

__device__ float g_scratch[NPOS * 128 * 64];     // [pos][b][o] 33.5 MB

typedef unsigned long long ull;

__device__ __forceinline__ void cp16(uint32_t dst, const float* src) {
    asm volatile("cp.async.ca.shared.global [%0], [%1], 16;\n" :: "r"(dst), "l"(src));
}
__device__ __forceinline__ void cp8(uint32_t dst, const float* src) {
    asm volatile("cp.async.ca.shared.global [%0], [%1], 8;\n" :: "r"(dst), "l"(src));
}
__device__ __forceinline__ void cp4(uint32_t dst, const float* src) {
    asm volatile("cp.async.ca.shared.global [%0], [%1], 4;\n" :: "r"(dst), "l"(src));
}
__device__ __forceinline__ void cp_commit() {
    asm volatile("cp.async.commit_group;\n");
}
template <int N>
__device__ __forceinline__ void cp_wait() {
    asm volatile("cp.async.wait_group %0;\n" :: "n"(N));
}
__device__ __forceinline__ ull pack2(float v) {
    ull r;
    asm("mov.b64 %0, {%1, %1};" : "=l"(r) : "f"(v));
    return r;
}
__device__ __forceinline__ void ffma2(ull& acc, ull a, ull b) {
    asm("fma.rn.f32x2 %0, %1, %2, %0;" : "+l"(acc) : "l"(a), "l"(b));
}

template <int C> __device__ __forceinline__ float fc(const float4& v);
template <> __device__ __forceinline__ float fc<0>(const float4& v) { return v.x; }
template <> __device__ __forceinline__ float fc<1>(const float4& v) { return v.y; }
template <> __device__ __forceinline__ float fc<2>(const float4& v) { return v.z; }
template <> __device__ __forceinline__ float fc<3>(const float4& v) { return v.w; }

// One (row, kj) step: 2 LDS.128 for W pairs, 8 A-dup movs, 32 FFMA2.
#define ROW_KJ(KJ)                                                        \
    {                                                                     \
        const float* wp = Wt + (rw * 3 + (KJ)) * 64 + 4 * nt;             \
        ulonglong2 w0 = *(const ulonglong2*)(wp);                         \
        ulonglong2 w1 = *(const ulonglong2*)(wp + 32);                    \
        _Pragma("unroll")                                                 \
        for (int u = 0; u < 8; ++u) {                                     \
            ull ad = pack2(fc<(KJ) + LEAD>(a[u]));                        \
            ffma2(acc[u][0], ad, w0.x);                                   \
            ffma2(acc[u][1], ad, w0.y);                                   \
            ffma2(acc[u][2], ad, w1.x);                                   \
            ffma2(acc[u][3], ad, w1.y);                                   \
        }                                                                 \
    }

template <int LEAD>
__device__ __forceinline__ void compute_chunk(const float4* __restrict__ A,
                                              const float*  __restrict__ Wt,
                                              int mt, int nt, ull acc[8][4]) {
    #pragma unroll 2
    for (int rw = 0; rw < RPC; ++rw) {
        float4 a[8];
        #pragma unroll
        for (int u = 0; u < 4; ++u) {
            a[u]     = A[rw * 128 + 4 * mt + u];
            a[4 + u] = A[rw * 128 + 64 + 4 * mt + u];
        }
        ROW_KJ(0)
        ROW_KJ(1)
        ROW_KJ(2)
    }
}

__global__ void __launch_bounds__(128, 3)
lc_gemm(const float* __restrict__ x,
        const float* __restrict__ w,
        const float* __restrict__ bias)
{
    extern __shared__ float sm[];
    float4* As = (float4*)sm;            // [2][RPC][128] float4 slots
    float*  Ws = sm + AS_FLOATS;         // [2][KKPC][64]

    const int pos = blockIdx.x;
    const int i = pos >> 5, j = pos & 31;
    const int tid = threadIdx.x;
    const int mt = tid >> 3, nt = tid & 7;
    const int lead = j & 1;              // block-constant A slot shift

    ull acc[8][4];
    #pragma unroll
    for (int u = 0; u < 8; ++u)
        #pragma unroll
        for (int q = 0; q < 4; ++q) acc[u][q] = 0ull;

    // ---- loaders ----
    // A: per r, all 128 threads load one (row, b=tid) 12B segment as 1-2 ops.
    auto loadA = [&](int t, int buf) {
        const int c0 = t * CPC;
        float4* dstA = As + buf * RPC * 128;
        #pragma unroll
        for (int r = 0; r < RPC; ++r) {
            const int cc = r / 3, ki = r - cc * 3;
            const float* sp =
                x + (((tid * CIN + c0 + cc) * HW) + (i + ki)) * HW + j - lead;
            uint32_t dst = (uint32_t)__cvta_generic_to_shared(dstA + r * 128 + tid);
            const int a4 = (j + 2 * ((i + ki) & 1)) & 3;   // uniform per r
            if (a4 <= 1) {
                cp16(dst, sp);                              // 4 floats, aligned
            } else {
                cp8(dst, sp);
                if (lead) cp8(dst + 8, sp + 2);
                else      cp4(dst + 8, sp + 2);
            }
        }
    };
    // W: 36B segments scattered -> 4B granules into [kk][o] (k-major, o contig).
    auto loadW = [&](int t, int buf) {
        const int c0 = t * CPC;
        float* dstW = Ws + buf * KKPC * 64;
        #pragma unroll
        for (int r = 0; r < 18; ++r) {                      // 18*128 = 36*64
            int s  = tid + 128 * r;
            int o  = s / KKPC;
            int kk = s - o * KKPC;
            int cc = kk / 9;
            int k9 = kk - cc * 9;
            const float* src =
                w + ((o * CIN + c0 + cc) * NPOS + pos) * 9 + k9;
            cp4((uint32_t)__cvta_generic_to_shared(dstW + kk * 64 + o), src);
        }
    };

    // ---- pipelined mainloop ----
    loadA(0, 0); loadW(0, 0); cp_commit();

    for (int t = 0; t < NCH; ++t) {
        if (t + 1 < NCH) {
            loadA(t + 1, (t + 1) & 1);
            loadW(t + 1, (t + 1) & 1);
            cp_commit();
            cp_wait<1>();
        } else {
            cp_wait<0>();
        }
        __syncthreads();

        const float4* A  = As + (t & 1) * RPC * 128;
        const float*  Wt = Ws + (t & 1) * KKPC * 64;
        if (lead) compute_chunk<1>(A, Wt, mt, nt, acc);
        else      compute_chunk<0>(A, Wt, mt, nt, acc);
        __syncthreads();
    }

    // ---- epilogue: bias + coalesced STG.128 into scratch[pos][b][o] ----
    float bv[8];
    #pragma unroll
    for (int q = 0; q < 4; ++q) {
        bv[q]     = bias[(4 * nt + q) * NPOS + pos];
        bv[4 + q] = bias[(32 + 4 * nt + q) * NPOS + pos];
    }
    float* sc = g_scratch + pos * (128 * 64);
    #pragma unroll
    for (int u = 0; u < 8; ++u) {
        const int b = (u < 4) ? (4 * mt + u) : (64 + 4 * mt + u - 4);
        #pragma unroll
        for (int g = 0; g < 2; ++g) {
            float2 p0 = *(float2*)&acc[u][2 * g];
            float2 p1 = *(float2*)&acc[u][2 * g + 1];
            float4 v;
            v.x = p0.x + bv[4 * g + 0];
            v.y = p0.y + bv[4 * g + 1];
            v.z = p1.x + bv[4 * g + 2];
            v.w = p1.y + bv[4 * g + 3];
            *(float4*)(sc + b * 64 + g * 32 + 4 * nt) = v;
        }
    }
}

// scratch[pos][bo] -> out[bo][pos], both sides fully coalesced.
__global__ void __launch_bounds__(256)
transpose_k(float* __restrict__ out)
{
    __shared__ float tile[32][33];
    const int bo0 = blockIdx.x * 32;
    const int p0  = blockIdx.y * 32;
    const int tx = threadIdx.x & 31, ty = threadIdx.x >> 5;
    #pragma unroll
    for (int r = ty; r < 32; r += 8)
        tile[r][tx] = g_scratch[(p0 + r) * (128 * 64) + bo0 + tx];
    __syncthreads();
    #pragma unroll
    for (int r = ty; r < 32; r += 8)
        out[(bo0 + r) * NPOS + p0 + tx] = tile[tx][r];
}

extern "C" void kernel_launch(void* const* d_in, const int* in_sizes, int n_in,
                              void* d_out, int out_size)
{
    (void)in_sizes; (void)n_in; (void)out_size;
    const float* x    = (const float*)d_in[0];
    const float* w    = (const float*)d_in[1];
    const float* bias = (const float*)d_in[2];
    float* out        = (float*)d_out;

    cudaFuncSetAttribute(lc_gemm,
                         cudaFuncAttributeMaxDynamicSharedMemorySize, SMEM_BYTES);
    lc_gemm<<<NPOS, 128, SMEM_BYTES>>>(x, w, bias);
    transpose_k<<<dim3(128 * 64 / 32, NPOS / 32), 256>>>(out);
}

// round 12
// speedup vs baseline: 1.6075x; 1.4971x over previous
#include <cuda_runtime.h>
#include <cstdint>

// out[b,o,i,j] = sum_{c,ki,kj} x[b,c,i+ki,j+kj] * w[o,c,i,j,ki*3+kj] + bias[o,i,j]
// x[128,32,34,34] f32, w[64,32,32,32,9], bias[64,32,32], out[128,64,32,32].
//
// Kernel 0 (transpose_x): x[b][chw] -> xT[chw][b]  (makes GEMM A-loads coalesced)
// Kernel 1 (lc_gemm): one block per (i,j). GEMM M=128(b) x N=64(o) x K=288.
//   128 threads, 8m x 8n tiles, f32x2 FMAs packed along n. A rows are
//   b-contiguous in xT -> perfectly coalesced cp.async.16B. Writes
//   scratch[pos][b][o] coalesced.
// Kernel 2 (transpose_k): scratch[pos][bo] -> out[bo][pos].

#define CIN   32
#define COUT  64
#define HW    34
#define NPOS  1024
#define CHW   (CIN*HW*HW)      // 36992
#define NCH   8                // K chunks
#define CPC   4                // input channels per chunk
#define RPC   36               // k-rows per chunk (CPC*9)

#define AS_FLOATS (2*RPC*128)  // 9216 floats (36864 B)
#define WS_FLOATS (2*RPC*64)   // 4608 floats (18432 B)
#define SMEM_BYTES ((AS_FLOATS + WS_FLOATS)*4)   // 55296 B

__device__ float g_xT[CHW * 128];              // [c][h][w][b] 18.9 MB
__device__ float g_scratch[NPOS * 128 * 64];   // [pos][b][o]  33.5 MB

typedef unsigned long long ull;

__device__ __forceinline__ void cp16(uint32_t dst, const float* src) {
    asm volatile("cp.async.ca.shared.global [%0], [%1], 16;\n" :: "r"(dst), "l"(src));
}
__device__ __forceinline__ void cp4(uint32_t dst, const float* src) {
    asm volatile("cp.async.ca.shared.global [%0], [%1], 4;\n" :: "r"(dst), "l"(src));
}
__device__ __forceinline__ void cp_commit() {
    asm volatile("cp.async.commit_group;\n");
}
template <int N>
__device__ __forceinline__ void cp_wait() {
    asm volatile("cp.async.wait_group %0;\n" :: "n"(N));
}
__device__ __forceinline__ ull pack2(float v) {
    ull r;
    asm("mov.b64 %0, {%1, %1};" : "=l"(r) : "f"(v));
    return r;
}
__device__ __forceinline__ void ffma2(ull& acc, ull a, ull b) {
    asm("fma.rn.f32x2 %0, %1, %2, %0;" : "+l"(acc) : "l"(a), "l"(b));
}

// ---- Kernel 0: x[128][36992] -> xT[36992][128] ----
__global__ void __launch_bounds__(256)
transpose_x(const float* __restrict__ x)
{
    __shared__ float tile[32][33];
    const int s0 = blockIdx.x * 32;        // chw base (1156 tiles, exact)
    const int b0 = blockIdx.y * 32;        // b base   (4 tiles)
    const int tx = threadIdx.x & 31, ty = threadIdx.x >> 5;
    #pragma unroll
    for (int r = ty; r < 32; r += 8)
        tile[r][tx] = x[(b0 + r) * CHW + s0 + tx];
    __syncthreads();
    #pragma unroll
    for (int r = ty; r < 32; r += 8)
        g_xT[(s0 + r) * 128 + b0 + tx] = tile[tx][r];
}

// ---- Kernel 1: per-position GEMM ----
__global__ void __launch_bounds__(128, 4)
lc_gemm(const float* __restrict__ w,
        const float* __restrict__ bias)
{
    extern __shared__ float sm[];
    float* As = sm;              // [2][RPC][128]  k-rows, b contiguous
    float* Ws = sm + AS_FLOATS;  // [2][RPC][64]   k-rows, o contiguous

    const int pos = blockIdx.x;
    const int i = pos >> 5, j = pos & 31;
    const int tid = threadIdx.x;
    const int mt = tid >> 3, nt = tid & 7;   // 16 m-threads x 8 n-threads

    ull acc[8][4];
    #pragma unroll
    for (int u = 0; u < 8; ++u)
        #pragma unroll
        for (int q = 0; q < 4; ++q) acc[u][q] = 0ull;

    // A: 36 rows x 128 floats, fully coalesced 16B granules (1152 cp16 / 128 thr).
    auto loadA = [&](int t, int buf) {
        const int c0 = t * CPC;
        float* dstA = As + buf * RPC * 128;
        #pragma unroll
        for (int q = 0; q < 9; ++q) {
            int s    = tid + 128 * q;
            int row  = s >> 5;            // 0..35 = cc*9 + ki*3 + kj
            int slot = (s & 31) * 4;      // b nibble
            int cc = row / 9, k9 = row - cc * 9;
            int ki = k9 / 3, kj = k9 - ki * 3;
            const float* src = g_xT +
                (((c0 + cc) * HW + (i + ki)) * HW + (j + kj)) * 128 + slot;
            cp16((uint32_t)__cvta_generic_to_shared(dstA + row * 128 + slot), src);
        }
    };
    // W: 36B gmem segments -> 4B granules into [kk][o] (k-major, o contiguous).
    auto loadW = [&](int t, int buf) {
        const int c0 = t * CPC;
        float* dstW = Ws + buf * RPC * 64;
        #pragma unroll
        for (int q = 0; q < 18; ++q) {    // 36*64 / 128
            int s  = tid + 128 * q;
            int o  = s / RPC;
            int kk = s - o * RPC;
            int cc = kk / 9, k9 = kk - cc * 9;
            const float* src = w + ((o * CIN + c0 + cc) * NPOS + pos) * 9 + k9;
            cp4((uint32_t)__cvta_generic_to_shared(dstW + kk * 64 + o), src);
        }
    };

    loadA(0, 0); loadW(0, 0); cp_commit();

    for (int t = 0; t < NCH; ++t) {
        if (t + 1 < NCH) {
            loadA(t + 1, (t + 1) & 1);
            loadW(t + 1, (t + 1) & 1);
            cp_commit();
            cp_wait<1>();
        } else {
            cp_wait<0>();
        }
        __syncthreads();

        const float* A  = As + (t & 1) * RPC * 128 + 8 * mt;
        const float* Wt = Ws + (t & 1) * RPC * 64 + 8 * nt;

        #pragma unroll 4
        for (int k = 0; k < RPC; ++k) {
            float4 a0 = *(const float4*)(A + k * 128);       // b 0..3 (8-lane bcast)
            float4 a1 = *(const float4*)(A + k * 128 + 4);   // b 4..7
            ulonglong2 w0 = *(const ulonglong2*)(Wt + k * 64);      // o-pairs 0,1
            ulonglong2 w1 = *(const ulonglong2*)(Wt + k * 64 + 4);  // o-pairs 2,3
            ull ad[8];
            ad[0] = pack2(a0.x); ad[1] = pack2(a0.y);
            ad[2] = pack2(a0.z); ad[3] = pack2(a0.w);
            ad[4] = pack2(a1.x); ad[5] = pack2(a1.y);
            ad[6] = pack2(a1.z); ad[7] = pack2(a1.w);
            #pragma unroll
            for (int u = 0; u < 8; ++u) {
                ffma2(acc[u][0], ad[u], w0.x);
                ffma2(acc[u][1], ad[u], w0.y);
                ffma2(acc[u][2], ad[u], w1.x);
                ffma2(acc[u][3], ad[u], w1.y);
            }
        }
        __syncthreads();
    }

    // Epilogue: bias + coalesced float4 stores into scratch[pos][b][o].
    float bv[8];
    #pragma unroll
    for (int q = 0; q < 8; ++q)
        bv[q] = bias[(8 * nt + q) * NPOS + pos];

    float* sc = g_scratch + pos * (128 * 64) + 8 * nt;
    #pragma unroll
    for (int u = 0; u < 8; ++u) {
        const int b = 8 * mt + u;
        #pragma unroll
        for (int g = 0; g < 2; ++g) {
            float2 p0 = *(float2*)&acc[u][2 * g];
            float2 p1 = *(float2*)&acc[u][2 * g + 1];
            float4 v;
            v.x = p0.x + bv[4 * g + 0];
            v.y = p0.y + bv[4 * g + 1];
            v.z = p1.x + bv[4 * g + 2];
            v.w = p1.y + bv[4 * g + 3];
            *(float4*)(sc + b * 64 + 4 * g) = v;
        }
    }
}

// ---- Kernel 2: scratch[pos][bo] -> out[bo][pos] ----
__global__ void __launch_bounds__(256)
transpose_k(float* __restrict__ out)
{
    __shared__ float tile[32][33];
    const int bo0 = blockIdx.x * 32;
    const int p0  = blockIdx.y * 32;
    const int tx = threadIdx.x & 31, ty = threadIdx.x >> 5;
    #pragma unroll
    for (int r = ty; r < 32; r += 8)
        tile[r][tx] = g_scratch[(p0 + r) * (128 * 64) + bo0 + tx];
    __syncthreads();
    #pragma unroll
    for (int r = ty; r < 32; r += 8)
        out[(bo0 + r) * NPOS + p0 + tx] = tile[tx][r];
}

extern "C" void kernel_launch(void* const* d_in, const int* in_sizes, int n_in,
                              void* d_out, int out_size)
{
    (void)in_sizes; (void)n_in; (void)out_size;
    const float* x    = (const float*)d_in[0];
    const float* w    = (const float*)d_in[1];
    const float* bias = (const float*)d_in[2];
    float* out        = (float*)d_out;

    cudaFuncSetAttribute(lc_gemm,
                         cudaFuncAttributeMaxDynamicSharedMemorySize, SMEM_BYTES);
    transpose_x<<<dim3(CHW / 32, 4), 256>>>(x);
    lc_gemm<<<NPOS, 128, SMEM_BYTES>>>(w, bias);
    transpose_k<<<dim3(128 * 64 / 32, NPOS / 32), 256>>>(out);
}

// round 13
// speedup vs baseline: 1.6110x; 1.0022x over previous
#include <cuda_runtime.h>
#include <cstdint>

// out[b,o,i,j] = sum_{c,ki,kj} x[b,c,i+ki,j+kj] * w[o,c,i,j,ki*3+kj] + bias[o,i,j]
// x[128,32,34,34] f32, w[64,32,32,32,9], bias[64,32,32], out[128,64,32,32].
//
// Kernel 0 (transpose_x): x[b][chw] -> xT[chw][b]  (makes GEMM A-loads coalesced)
// Kernel 1 (lc_gemm): one block per (i,j). GEMM M=128(b) x N=64(o) x K=288.
//   128 threads, 8m x 8n tiles, f32x2 FMAs packed along n. A rows are
//   b-contiguous in xT -> perfectly coalesced cp.async.16B. Writes
//   scratch[pos][b][o] coalesced.
// Kernel 2 (transpose_k): scratch[pos][bo] -> out[bo][pos].

#define CIN   32
#define COUT  64
#define HW    34
#define NPOS  1024
#define CHW   (CIN*HW*HW)      // 36992
#define NCH   8                // K chunks
#define CPC   4                // input channels per chunk
#define RPC   36               // k-rows per chunk (CPC*9)

#define AS_FLOATS (2*RPC*128)  // 9216 floats (36864 B)
#define WS_FLOATS (2*RPC*64)   // 4608 floats (18432 B)
#define SMEM_BYTES ((AS_FLOATS + WS_FLOATS)*4)   // 55296 B

__device__ float g_xT[CHW * 128];              // [c][h][w][b] 18.9 MB
__device__ float g_scratch[NPOS * 128 * 64];   // [pos][b][o]  33.5 MB

typedef unsigned long long ull;

__device__ __forceinline__ void cp16(uint32_t dst, const float* src) {
    asm volatile("cp.async.ca.shared.global [%0], [%1], 16;\n" :: "r"(dst), "l"(src));
}
__device__ __forceinline__ void cp4(uint32_t dst, const float* src) {
    asm volatile("cp.async.ca.shared.global [%0], [%1], 4;\n" :: "r"(dst), "l"(src));
}
__device__ __forceinline__ void cp_commit() {
    asm volatile("cp.async.commit_group;\n");
}
template <int N>
__device__ __forceinline__ void cp_wait() {
    asm volatile("cp.async.wait_group %0;\n" :: "n"(N));
}
__device__ __forceinline__ ull pack2(float v) {
    ull r;
    asm("mov.b64 %0, {%1, %1};" : "=l"(r) : "f"(v));
    return r;
}
__device__ __forceinline__ void ffma2(ull& acc, ull a, ull b) {
    asm("fma.rn.f32x2 %0, %1, %2, %0;" : "+l"(acc) : "l"(a), "l"(b));
}

// ---- Kernel 0: x[128][36992] -> xT[36992][128] ----
__global__ void __launch_bounds__(256)
transpose_x(const float* __restrict__ x)
{
    __shared__ float tile[32][33];
    const int s0 = blockIdx.x * 32;        // chw base (1156 tiles, exact)
    const int b0 = blockIdx.y * 32;        // b base   (4 tiles)
    const int tx = threadIdx.x & 31, ty = threadIdx.x >> 5;
    #pragma unroll
    for (int r = ty; r < 32; r += 8)
        tile[r][tx] = x[(b0 + r) * CHW + s0 + tx];
    __syncthreads();
    #pragma unroll
    for (int r = ty; r < 32; r += 8)
        g_xT[(s0 + r) * 128 + b0 + tx] = tile[tx][r];
}

// ---- Kernel 1: per-position GEMM ----
__global__ void __launch_bounds__(128, 4)
lc_gemm(const float* __restrict__ w,
        const float* __restrict__ bias)
{
    extern __shared__ float sm[];
    float* As = sm;              // [2][RPC][128]  k-rows, b contiguous
    float* Ws = sm + AS_FLOATS;  // [2][RPC][64]   k-rows, o contiguous

    const int pos = blockIdx.x;
    const int i = pos >> 5, j = pos & 31;
    const int tid = threadIdx.x;
    const int mt = tid >> 3, nt = tid & 7;   // 16 m-threads x 8 n-threads

    ull acc[8][4];
    #pragma unroll
    for (int u = 0; u < 8; ++u)
        #pragma unroll
        for (int q = 0; q < 4; ++q) acc[u][q] = 0ull;

    // A: 36 rows x 128 floats, fully coalesced 16B granules (1152 cp16 / 128 thr).
    auto loadA = [&](int t, int buf) {
        const int c0 = t * CPC;
        float* dstA = As + buf * RPC * 128;
        #pragma unroll
        for (int q = 0; q < 9; ++q) {
            int s    = tid + 128 * q;
            int row  = s >> 5;            // 0..35 = cc*9 + ki*3 + kj
            int slot = (s & 31) * 4;      // b nibble
            int cc = row / 9, k9 = row - cc * 9;
            int ki = k9 / 3, kj = k9 - ki * 3;
            const float* src = g_xT +
                (((c0 + cc) * HW + (i + ki)) * HW + (j + kj)) * 128 + slot;
            cp16((uint32_t)__cvta_generic_to_shared(dstA + row * 128 + slot), src);
        }
    };
    // W: 36B gmem segments -> 4B granules into [kk][o] (k-major, o contiguous).
    auto loadW = [&](int t, int buf) {
        const int c0 = t * CPC;
        float* dstW = Ws + buf * RPC * 64;
        #pragma unroll
        for (int q = 0; q < 18; ++q) {    // 36*64 / 128
            int s  = tid + 128 * q;
            int o  = s / RPC;
            int kk = s - o * RPC;
            int cc = kk / 9, k9 = kk - cc * 9;
            const float* src = w + ((o * CIN + c0 + cc) * NPOS + pos) * 9 + k9;
            cp4((uint32_t)__cvta_generic_to_shared(dstW + kk * 64 + o), src);
        }
    };

    loadA(0, 0); loadW(0, 0); cp_commit();

    for (int t = 0; t < NCH; ++t) {
        if (t + 1 < NCH) {
            loadA(t + 1, (t + 1) & 1);
            loadW(t + 1, (t + 1) & 1);
            cp_commit();
            cp_wait<1>();
        } else {
            cp_wait<0>();
        }
        __syncthreads();

        const float* A  = As + (t & 1) * RPC * 128 + 8 * mt;
        const float* Wt = Ws + (t & 1) * RPC * 64 + 8 * nt;

        #pragma unroll 4
        for (int k = 0; k < RPC; ++k) {
            float4 a0 = *(const float4*)(A + k * 128);       // b 0..3 (8-lane bcast)
            float4 a1 = *(const float4*)(A + k * 128 + 4);   // b 4..7
            ulonglong2 w0 = *(const ulonglong2*)(Wt + k * 64);      // o-pairs 0,1
            ulonglong2 w1 = *(const ulonglong2*)(Wt + k * 64 + 4);  // o-pairs 2,3
            ull ad[8];
            ad[0] = pack2(a0.x); ad[1] = pack2(a0.y);
            ad[2] = pack2(a0.z); ad[3] = pack2(a0.w);
            ad[4] = pack2(a1.x); ad[5] = pack2(a1.y);
            ad[6] = pack2(a1.z); ad[7] = pack2(a1.w);
            #pragma unroll
            for (int u = 0; u < 8; ++u) {
                ffma2(acc[u][0], ad[u], w0.x);
                ffma2(acc[u][1], ad[u], w0.y);
                ffma2(acc[u][2], ad[u], w1.x);
                ffma2(acc[u][3], ad[u], w1.y);
            }
        }
        __syncthreads();
    }

    // Epilogue: bias + coalesced float4 stores into scratch[pos][b][o].
    float bv[8];
    #pragma unroll
    for (int q = 0; q < 8; ++q)
        bv[q] = bias[(8 * nt + q) * NPOS + pos];

    float* sc = g_scratch + pos * (128 * 64) + 8 * nt;
    #pragma unroll
    for (int u = 0; u < 8; ++u) {
        const int b = 8 * mt + u;
        #pragma unroll
        for (int g = 0; g < 2; ++g) {
            float2 p0 = *(float2*)&acc[u][2 * g];
            float2 p1 = *(float2*)&acc[u][2 * g + 1];
            float4 v;
            v.x = p0.x + bv[4 * g + 0];
            v.y = p0.y + bv[4 * g + 1];
            v.z = p1.x + bv[4 * g + 2];
            v.w = p1.y + bv[4 * g + 3];
            *(float4*)(sc + b * 64 + 4 * g) = v;
        }
    }
}

// ---- Kernel 2: scratch[pos][bo] -> out[bo][pos] ----
__global__ void __launch_bounds__(256)
transpose_k(float* __restrict__ out)
{
    __shared__ float tile[32][33];
    const int bo0 = blockIdx.x * 32;
    const int p0  = blockIdx.y * 32;
    const int tx = threadIdx.x & 31, ty = threadIdx.x >> 5;
    #pragma unroll
    for (int r = ty; r < 32; r += 8)
        tile[r][tx] = g_scratch[(p0 + r) * (128 * 64) + bo0 + tx];
    __syncthreads();
    #pragma unroll
    for (int r = ty; r < 32; r += 8)
        out[(bo0 + r) * NPOS + p0 + tx] = tile[tx][r];
}

extern "C" void kernel_launch(void* const* d_in, const int* in_sizes, int n_in,
                              void* d_out, int out_size)
{
    (void)in_sizes; (void)n_in; (void)out_size;
    const float* x    = (const float*)d_in[0];
    const float* w    = (const float*)d_in[1];
    const float* bias = (const float*)d_in[2];
    float* out        = (float*)d_out;

    cudaFuncSetAttribute(lc_gemm,
                         cudaFuncAttributeMaxDynamicSharedMemorySize, SMEM_BYTES);
    transpose_x<<<dim3(CHW / 32, 4), 256>>>(x);
    lc_gemm<<<NPOS, 128, SMEM_BYTES>>>(w, bias);
    transpose_k<<<dim3(128 * 64 / 32, NPOS / 32), 256>>>(out);
}